// round 1
// baseline (speedup 1.0000x reference)
#include <cuda_runtime.h>
#include <cuda_fp16.h>
#include <cstdint>
#include <cstdio>

#define B_SZ   1024
#define IN_SZ  128
#define OUT_SZ 10000
#define OUTP   10112            // 79 * 128, padded
#define KCEN   16
#define SSC    64.0f

#define LDA 136                 // 128 + 8 halves pad -> conflict-free ldmatrix
#define LDB 136
#define ATILE (128*LDA)
#define BTILE (128*LDB)
#define SMEM_HALVES (ATILE + 2*BTILE)
#define SMEM_BYTES  (SMEM_HALVES*2)

// ---------------- device scratch (static, 16B-aligned via float4) ----------
__device__ float4 g_xh4[(B_SZ*IN_SZ)/8];                       // 256 KB fp16
__device__ float4 g_wh4[((size_t)KCEN*IN_SZ*OUTP)/8];          // 41.4 MB fp16 (normalized)
__device__ float  g_cos[(size_t)B_SZ*OUTP];                    // 41.4 MB fp32
__device__ float  g_cosfa[B_SZ], g_sinfa[B_SZ], g_costhr[B_SZ];
__device__ float  g_loss[B_SZ], g_corr[B_SZ];

// ---------------- prep: normalize input rows, per-row margin consts --------
__global__ void prep_x_kernel(const float* __restrict__ x,
                              const float* __restrict__ factor) {
    int b = blockIdx.x, f = threadIdx.x;     // 128 threads
    float v = x[b*IN_SZ + f];
    float s = v*v;
    #pragma unroll
    for (int o = 16; o; o >>= 1) s += __shfl_xor_sync(0xffffffffu, s, o);
    __shared__ float ws[4];
    if ((f & 31) == 0) ws[f >> 5] = s;
    __syncthreads();
    float tot = ws[0] + ws[1] + ws[2] + ws[3];
    float rinv = 1.f / fmaxf(sqrtf(tot), 1e-12f);
    ((__half*)g_xh4)[b*IN_SZ + f] = __float2half(v * rinv);
    if (f == 0) {
        float fa = powf(1.5f, factor[b] * (1.f/12.f)) * 0.5f;
        float cfa = cosf(fa);
        g_cosfa[b] = cfa;
        g_sinfa[b] = sinf(fa);
        g_costhr[b] = -cfa;                  // cos(pi - fa)
    }
}

// ---------------- prep: normalize weight columns -> fp16, zero the pad -----
__global__ void prep_w_kernel(const float* __restrict__ w) {
    int idx = blockIdx.x*blockDim.x + threadIdx.x;
    if (idx >= KCEN*OUTP) return;
    int k = idx / OUTP, o = idx % OUTP;
    __half* wh = (__half*)g_wh4;
    size_t base = (size_t)k*IN_SZ*OUTP + o;
    if (o >= OUT_SZ) {
        for (int f = 0; f < IN_SZ; f++) wh[base + (size_t)f*OUTP] = __float2half(0.f);
        return;
    }
    const float* col = w + (size_t)k*IN_SZ*OUT_SZ + o;
    float s = 0.f;
    #pragma unroll 8
    for (int f = 0; f < IN_SZ; f++) { float v = col[(size_t)f*OUT_SZ]; s += v*v; }
    float rinv = 1.f / fmaxf(sqrtf(s), 1e-12f);
    #pragma unroll 8
    for (int f = 0; f < IN_SZ; f++)
        wh[base + (size_t)f*OUTP] = __float2half(col[(size_t)f*OUT_SZ] * rinv);
}

// ---------------- GEMM helpers ---------------------------------------------
__device__ __forceinline__ void cp_async16(uint32_t saddr, const void* gptr) {
    asm volatile("cp.async.cg.shared.global [%0], [%1], 16;\n" :: "r"(saddr), "l"(gptr));
}
#define CP_COMMIT() asm volatile("cp.async.commit_group;\n")
#define CP_WAIT1()  asm volatile("cp.async.wait_group 1;\n")

#define LDSM_X4(r0,r1,r2,r3,addr) \
    asm volatile("ldmatrix.sync.aligned.m8n8.x4.shared.b16 {%0,%1,%2,%3}, [%4];" \
        : "=r"(r0),"=r"(r1),"=r"(r2),"=r"(r3) : "r"(addr))
#define LDSM_X4_T(r0,r1,r2,r3,addr) \
    asm volatile("ldmatrix.sync.aligned.m8n8.x4.trans.shared.b16 {%0,%1,%2,%3}, [%4];" \
        : "=r"(r0),"=r"(r1),"=r"(r2),"=r"(r3) : "r"(addr))
#define MMA16816(c0,c1,c2,c3,a0,a1,a2,a3,b0,b1) \
    asm volatile("mma.sync.aligned.m16n8k16.row.col.f32.f16.f16.f32 " \
        "{%0,%1,%2,%3},{%4,%5,%6,%7},{%8,%9},{%0,%1,%2,%3};" \
        : "+f"(c0),"+f"(c1),"+f"(c2),"+f"(c3) \
        : "r"(a0),"r"(a1),"r"(a2),"r"(a3),"r"(b0),"r"(b1))

__device__ __forceinline__ void load_b_tile(__half* Bs, const __half* wh,
                                            int tid, int n0, int kc, int buf) {
    int chunk = tid & 15, r0 = tid >> 4;
    const __half* src = wh + (size_t)kc*IN_SZ*OUTP + n0;
    __half* dst = Bs + buf*BTILE;
    #pragma unroll
    for (int it = 0; it < 8; it++) {
        int row = it*16 + r0;
        cp_async16((uint32_t)__cvta_generic_to_shared(dst + row*LDB + chunk*8),
                   src + (size_t)row*OUTP + chunk*8);
    }
}

// ---------------- main GEMM: cos[b][o] = max_k <xn_b, wn_{k,:,o}> ----------
__global__ void __launch_bounds__(256, 1) gemm_kernel() {
    extern __shared__ __half sm[];
    __half* As = sm;
    __half* Bs = sm + ATILE;
    const __half* xh = (const __half*)g_xh4;
    const __half* wh = (const __half*)g_wh4;

    int tid = threadIdx.x;
    int n0 = blockIdx.x * 128;
    int m0 = blockIdx.y * 128;

    // A tile (reused for all 16 k-centers)
    {
        int chunk = tid & 15, r0 = tid >> 4;
        #pragma unroll
        for (int it = 0; it < 8; it++) {
            int row = it*16 + r0;
            cp_async16((uint32_t)__cvta_generic_to_shared(As + row*LDA + chunk*8),
                       xh + (size_t)(m0 + row)*IN_SZ + chunk*8);
        }
    }
    load_b_tile(Bs, wh, tid, n0, 0, 0);
    CP_COMMIT();                              // group0 = A + B0

    int wid = tid >> 5, lane = tid & 31;
    int wm = wid & 3, wn = wid >> 2;          // warp tile: 32 rows x 64 cols

    uint32_t smem_u32 = (uint32_t)__cvta_generic_to_shared(sm);
    uint32_t aA = smem_u32 + ((wm*32 + (lane & 15))*LDA + (lane >> 4)*8)*2;
    uint32_t aB = smem_u32 + ATILE*2 + ((lane & 15)*LDB + wn*64 + (lane >> 4)*8)*2;

    float mx[2][8][4];
    #pragma unroll
    for (int i = 0; i < 2; i++)
        #pragma unroll
        for (int j = 0; j < 8; j++)
            #pragma unroll
            for (int c = 0; c < 4; c++) mx[i][j][c] = -3.4e38f;

    for (int kc = 0; kc < KCEN; kc++) {
        int buf = kc & 1;
        if (kc < KCEN-1) load_b_tile(Bs, wh, tid, n0, kc+1, buf ^ 1);
        CP_COMMIT();
        CP_WAIT1();
        __syncthreads();

        float acc[2][8][4];
        #pragma unroll
        for (int i = 0; i < 2; i++)
            #pragma unroll
            for (int j = 0; j < 8; j++)
                #pragma unroll
                for (int c = 0; c < 4; c++) acc[i][j][c] = 0.f;

        #pragma unroll
        for (int ks = 0; ks < 8; ks++) {
            uint32_t a[2][4];
            #pragma unroll
            for (int mt = 0; mt < 2; mt++)
                LDSM_X4(a[mt][0], a[mt][1], a[mt][2], a[mt][3],
                        aA + mt*16*LDA*2 + ks*32);
            uint32_t bq[8][2];
            #pragma unroll
            for (int p = 0; p < 4; p++)
                LDSM_X4_T(bq[2*p][0], bq[2*p][1], bq[2*p+1][0], bq[2*p+1][1],
                          aB + buf*BTILE*2 + ks*16*LDB*2 + p*32);
            #pragma unroll
            for (int mt = 0; mt < 2; mt++)
                #pragma unroll
                for (int nt = 0; nt < 8; nt++)
                    MMA16816(acc[mt][nt][0], acc[mt][nt][1], acc[mt][nt][2], acc[mt][nt][3],
                             a[mt][0], a[mt][1], a[mt][2], a[mt][3],
                             bq[nt][0], bq[nt][1]);
        }
        #pragma unroll
        for (int i = 0; i < 2; i++)
            #pragma unroll
            for (int j = 0; j < 8; j++)
                #pragma unroll
                for (int c = 0; c < 4; c++)
                    mx[i][j][c] = fmaxf(mx[i][j][c], acc[i][j][c]);
        __syncthreads();
    }

    int rbase = m0 + wm*32 + (lane >> 2);
    int cbase = n0 + wn*64 + (lane & 3)*2;
    #pragma unroll
    for (int mt = 0; mt < 2; mt++)
        #pragma unroll
        for (int nt = 0; nt < 8; nt++) {
            int r = rbase + mt*16, c = cbase + nt*8;
            *(float2*)&g_cos[(size_t)r*OUTP + c]      = make_float2(mx[mt][nt][0], mx[mt][nt][1]);
            *(float2*)&g_cos[(size_t)(r+8)*OUTP + c]  = make_float2(mx[mt][nt][2], mx[mt][nt][3]);
        }
}

// ---------------- per-row epilogue: margin + online log-softmax + argmax ---
__global__ void epi_kernel(const int* __restrict__ label) {
    int b = blockIdx.x, t = threadIdx.x;     // 256 threads
    int lab = label[b];
    float cfa = g_cosfa[b], sfa = g_sinfa[b], cthr = g_costhr[b];
    const float* row = g_cos + (size_t)b*OUTP;

    const float CLO = -1.0f + 1e-6f, CHI = 1.0f - 1e-6f;
    float m = -3.4e38f, s = 0.f; int am = 0x7fffffff;
    __shared__ float s_lab;

    for (int o = t; o < OUT_SZ; o += 256) {
        float c = row[o];
        c = fminf(fmaxf(c, CLO), CHI);
        float l = c * SSC;
        if (o == lab) {
            if (c >= cthr)     // theta <= threshold -> apply margin
                l = (c*cfa - sqrtf(fmaxf(1.f - c*c, 0.f))*sfa) * SSC;
            s_lab = l;
        }
        if (l > m) { s = s*__expf(m - l) + 1.f; m = l; am = o; }
        else       { s += __expf(l - m); }
    }

    __shared__ float rm[256], rs[256];
    __shared__ int   ra[256];
    rm[t] = m; rs[t] = s; ra[t] = am;
    __syncthreads();
    for (int st = 128; st > 0; st >>= 1) {
        if (t < st) {
            float m1 = rm[t], s1 = rs[t];  int a1 = ra[t];
            float m2 = rm[t+st], s2 = rs[t+st]; int a2 = ra[t+st];
            float M = fmaxf(m1, m2);
            rs[t] = s1*__expf(m1 - M) + s2*__expf(m2 - M);
            rm[t] = M;
            ra[t] = (m2 > m1 || (m2 == m1 && a2 < a1)) ? a2 : a1;
        }
        __syncthreads();
    }
    if (t == 0) {
        g_loss[b] = logf(rs[0]) + rm[0] - s_lab;
        g_corr[b] = (ra[0] == lab) ? 1.f : 0.f;
    }
}

// ---------------- final reduction ------------------------------------------
__global__ void fin_kernel(float* __restrict__ out) {
    int t = threadIdx.x;                     // 1024 threads
    __shared__ float sl[1024], sc[1024];
    sl[t] = g_loss[t]; sc[t] = g_corr[t];
    __syncthreads();
    for (int st = 512; st > 0; st >>= 1) {
        if (t < st) { sl[t] += sl[t+st]; sc[t] += sc[t+st]; }
        __syncthreads();
    }
    if (t == 0) {
        out[0] = sl[0] * (1.f/1024.f);
        out[1] = sc[0] * (100.f/1024.f);
    }
}

// ---------------- launch ----------------------------------------------------
extern "C" void kernel_launch(void* const* d_in, const int* in_sizes, int n_in,
                              void* d_out, int out_size) {
    const float* x      = (const float*)d_in[0];
    const float* factor = (const float*)d_in[1];
    const int*   label  = (const int*)  d_in[2];
    const float* w      = (const float*)d_in[3];
    float* out = (float*)d_out;

    cudaFuncSetAttribute(gemm_kernel, cudaFuncAttributeMaxDynamicSharedMemorySize, SMEM_BYTES);

    prep_x_kernel<<<B_SZ, 128>>>(x, factor);
    prep_w_kernel<<<(KCEN*OUTP + 255)/256, 256>>>(w);
    gemm_kernel<<<dim3(OUTP/128, B_SZ/128), 256, SMEM_BYTES>>>();
    epi_kernel<<<B_SZ, 256>>>(label);
    fin_kernel<<<1, 1024>>>(out);
}